// round 1
// baseline (speedup 1.0000x reference)
#include <cuda_runtime.h>
#include <cuda_bf16.h>

#define NPTS    32768
#define PK      16          // kernel points == neighbors per center
#define NCENT   8192
#define IN_F    64
#define OUT_F   128
#define BM      64          // centers per block
#define NTHREADS 256
#define ASTRIDE 65          // padded A stride (odd -> conflict-free broadcast reads)

// dynamic smem layout (floats):
//  As   [BM][ASTRIDE]      4160
//  Bs   [IN_F][OUT_F]      8192
//  coef [BM][PK]           1024
//  kpts [64]               48 used
//  srcs [BM][PK] (int)     1024
__global__ __launch_bounds__(NTHREADS) void kpconv_kernel(
    const float* __restrict__ x,
    const float* __restrict__ pos,
    const int*   __restrict__ edge_src,
    const int*   __restrict__ edge_tgt,
    const float* __restrict__ kernel_pts,
    const float* __restrict__ kernel_weight,
    float* __restrict__ out)
{
    extern __shared__ float smem[];
    float* As   = smem;                     // BM*ASTRIDE
    float* Bs   = As + BM * ASTRIDE;        // IN_F*OUT_F
    float* coef = Bs + IN_F * OUT_F;        // BM*PK
    float* kpts = coef + BM * PK;           // 64
    int*   srcs = (int*)(kpts + 64);        // BM*PK

    const int tid = threadIdx.x;
    const int c0  = blockIdx.x * BM;

    if (tid < PK * 3) kpts[tid] = kernel_pts[tid];
    for (int i = tid; i < BM * PK; i += NTHREADS) coef[i] = 0.0f;
    __syncthreads();

    // ---- geometry: per-edge argmin kernel point + linear influence weight ----
    #pragma unroll
    for (int j = 0; j < (BM * PK) / NTHREADS; j++) {
        int el = tid + j * NTHREADS;        // local edge 0..1023
        int e  = c0 * PK + el;
        int s  = edge_src[e];
        int t  = edge_tgt[e];
        srcs[el] = s;
        float rx = pos[3 * t + 0] - pos[3 * s + 0];
        float ry = pos[3 * t + 1] - pos[3 * s + 1];
        float rz = pos[3 * t + 2] - pos[3 * s + 2];
        float best = 3.4e38f; int bk = 0;
        #pragma unroll
        for (int kp = 0; kp < PK; kp++) {
            float dx = rx - kpts[3 * kp + 0];
            float dy = ry - kpts[3 * kp + 1];
            float dz = rz - kpts[3 * kp + 2];
            float d2 = dx * dx + dy * dy + dz * dz;
            if (d2 < best) { best = d2; bk = kp; }
        }
        float w = fmaxf(1.0f - sqrtf(best) * 1.5f, 0.0f);  // 1/KP_EXTENT = 1.5
        atomicAdd(&coef[(el & ~(PK - 1)) + bk], w);
    }
    __syncthreads();

    // ---- fused GEMM: out[c,:] = sum_k coef[c,k] * x[srcs[c,k]] @ W[k] ----
    const int ty = tid >> 4;      // 0..15 -> rows ty*4..+3
    const int tx = tid & 15;      // 0..15 -> cols tx*8..+7

    float acc[4][8];
    #pragma unroll
    for (int r = 0; r < 4; r++)
        #pragma unroll
        for (int c = 0; c < 8; c++) acc[r][c] = 0.0f;

    #pragma unroll 1
    for (int k = 0; k < PK; k++) {
        // A tile: As[c][i] = coef[c][k] * x[srcs[c][k]][i]   (64 x 64)
        #pragma unroll
        for (int j = 0; j < 4; j++) {
            int s4 = tid + j * NTHREADS;    // float4 slot 0..1023
            int c  = s4 >> 4;
            int i4 = s4 & 15;
            int sidx = srcs[c * PK + k];
            float sc = coef[c * PK + k];
            float4 v = *reinterpret_cast<const float4*>(
                x + (size_t)sidx * IN_F + i4 * 4);
            float* d = As + c * ASTRIDE + i4 * 4;
            d[0] = v.x * sc; d[1] = v.y * sc; d[2] = v.z * sc; d[3] = v.w * sc;
        }
        // B tile: Bs[i][o] = W[k][i][o]   (64 x 128)
        const float* wptr = kernel_weight + (size_t)k * IN_F * OUT_F;
        #pragma unroll
        for (int j = 0; j < 8; j++) {
            int s4 = tid + j * NTHREADS;    // float4 slot 0..2047
            int i  = s4 >> 5;
            int o4 = s4 & 31;
            *reinterpret_cast<float4*>(Bs + i * OUT_F + o4 * 4) =
                *reinterpret_cast<const float4*>(wptr + i * OUT_F + o4 * 4);
        }
        __syncthreads();

        #pragma unroll 16
        for (int kk = 0; kk < IN_F; kk++) {
            float a[4];
            #pragma unroll
            for (int r = 0; r < 4; r++)
                a[r] = As[(ty * 4 + r) * ASTRIDE + kk];
            float4 b0 = *reinterpret_cast<const float4*>(Bs + kk * OUT_F + tx * 8);
            float4 b1 = *reinterpret_cast<const float4*>(Bs + kk * OUT_F + tx * 8 + 4);
            float b[8] = {b0.x, b0.y, b0.z, b0.w, b1.x, b1.y, b1.z, b1.w};
            #pragma unroll
            for (int r = 0; r < 4; r++)
                #pragma unroll
                for (int c = 0; c < 8; c++)
                    acc[r][c] = fmaf(a[r], b[c], acc[r][c]);
        }
        __syncthreads();
    }

    // ---- epilogue ----
    #pragma unroll
    for (int r = 0; r < 4; r++) {
        int row = c0 + ty * 4 + r;
        float* op = out + (size_t)row * OUT_F + tx * 8;
        float4 v0 = make_float4(acc[r][0], acc[r][1], acc[r][2], acc[r][3]);
        float4 v1 = make_float4(acc[r][4], acc[r][5], acc[r][6], acc[r][7]);
        *reinterpret_cast<float4*>(op)     = v0;
        *reinterpret_cast<float4*>(op + 4) = v1;
    }
}

extern "C" void kernel_launch(void* const* d_in, const int* in_sizes, int n_in,
                              void* d_out, int out_size) {
    const float* x             = (const float*)d_in[0];
    const float* pos           = (const float*)d_in[1];
    const int*   edge_src      = (const int*)d_in[2];
    const int*   edge_tgt      = (const int*)d_in[3];
    const float* kernel_pts    = (const float*)d_in[4];
    const float* kernel_weight = (const float*)d_in[5];
    float* out = (float*)d_out;

    int smem_bytes = (BM * ASTRIDE + IN_F * OUT_F + BM * PK + 64) * 4
                     + BM * PK * 4;  // + srcs (int)
    cudaFuncSetAttribute(kpconv_kernel,
                         cudaFuncAttributeMaxDynamicSharedMemorySize, smem_bytes);
    kpconv_kernel<<<NCENT / BM, NTHREADS, smem_bytes>>>(
        x, pos, edge_src, edge_tgt, kernel_pts, kernel_weight, out);
}

// round 5
// speedup vs baseline: 2.7986x; 2.7986x over previous
#include <cuda_runtime.h>
#include <cuda_bf16.h>
#include <cstdint>

#define PK      16
#define NCENT   8192
#define IN_F    64
#define OUT_F   128
#define M_TILE  64
#define NTH     256
#define LDB     144          // smem row pitch bytes (64 bf16 + 8 pad)

// pre-split, pre-transposed weights: Wt[k][o][i] = W[k][i][o] as bf16 hi/lo
__device__ __align__(128) __nv_bfloat16 g_wt_hi[PK * OUT_F * IN_F];
__device__ __align__(128) __nv_bfloat16 g_wt_lo[PK * OUT_F * IN_F];

// ---------------- smem layout (bytes), single stage --------------------------
#define SM_KPTS   0                        // 48 floats
#define SM_COEF   256                      // 64*16 f32 = 4096
#define SM_SRCS   (SM_COEF + 4096)         // 64*16 int = 4096
#define SM_TILES  8704
#define A_BYTES   (M_TILE * LDB)           // 9216
#define B_BYTES   (OUT_F * LDB)            // 18432
#define AH_OFF    SM_TILES
#define AL_OFF    (AH_OFF + A_BYTES)
#define BH_OFF    (AL_OFF + A_BYTES)
#define BL_OFF    (BH_OFF + B_BYTES)
#define SM_TOTAL  (BL_OFF + B_BYTES)       // 64000

// ---------------- PTX helpers ------------------------------------------------
__device__ __forceinline__ uint32_t smem_u32(const void* p) {
    uint32_t a;
    asm("{ .reg .u64 t; cvta.to.shared.u64 t, %1; cvt.u32.u64 %0, t; }"
        : "=r"(a) : "l"(p));
    return a;
}
__device__ __forceinline__ void ldsm4(uint32_t* r, uint32_t addr) {
    asm volatile("ldmatrix.sync.aligned.m8n8.x4.shared.b16 {%0,%1,%2,%3}, [%4];"
                 : "=r"(r[0]), "=r"(r[1]), "=r"(r[2]), "=r"(r[3]) : "r"(addr));
}
__device__ __forceinline__ void mma_bf16(float* c, const uint32_t* a, const uint32_t* b) {
    asm volatile("mma.sync.aligned.m16n8k16.row.col.f32.bf16.bf16.f32 "
                 "{%0,%1,%2,%3}, {%4,%5,%6,%7}, {%8,%9}, {%0,%1,%2,%3};"
                 : "+f"(c[0]), "+f"(c[1]), "+f"(c[2]), "+f"(c[3])
                 : "r"(a[0]), "r"(a[1]), "r"(a[2]), "r"(a[3]),
                   "r"(b[0]), "r"(b[1]));
}

// ---------------- pre-kernel: W -> Wt_hi/Wt_lo -------------------------------
__global__ void wsplit_kernel(const float* __restrict__ w) {
    int idx = blockIdx.x * blockDim.x + threadIdx.x;
    if (idx >= PK * OUT_F * IN_F) return;
    int k = idx >> 13, rem = idx & 8191;
    int o = rem >> 6, i = rem & 63;
    float v = w[k * (IN_F * OUT_F) + i * OUT_F + o];
    __nv_bfloat16 h = __float2bfloat16(v);
    g_wt_hi[idx] = h;
    g_wt_lo[idx] = __float2bfloat16(v - __bfloat162float(h));
}

// ---------------- main fused kernel ------------------------------------------
__global__ __launch_bounds__(NTH, 1) void kpconv_hmma_kernel(
    const float* __restrict__ x,
    const float* __restrict__ pos,
    const int*   __restrict__ edge_src,
    const int*   __restrict__ edge_tgt,
    const float* __restrict__ kernel_pts,
    float* __restrict__ out)
{
    extern __shared__ char sm[];
    const uint32_t smb = smem_u32(sm);
    float* s_kpts = (float*)(sm + SM_KPTS);
    float* s_coef = (float*)(sm + SM_COEF);
    int*   s_srcs = (int*)(sm + SM_SRCS);

    const int tid  = threadIdx.x;
    const int wid  = tid >> 5;
    const int lane = tid & 31;
    const int c0   = blockIdx.x * M_TILE;

    if (tid < PK * 3) s_kpts[tid] = kernel_pts[tid];
    for (int i = tid; i < M_TILE * PK; i += NTH) s_coef[i] = 0.0f;
    __syncthreads();

    // ---- geometry: argmin kernel point + linear influence -> coef/srcs -----
    #pragma unroll
    for (int j = 0; j < (M_TILE * PK) / NTH; j++) {
        int el = tid + j * NTH;                 // local edge 0..1023
        int e  = c0 * PK + el;
        int s  = edge_src[e];
        int t  = edge_tgt[e];
        s_srcs[el] = s;
        float rx = pos[3 * t + 0] - pos[3 * s + 0];
        float ry = pos[3 * t + 1] - pos[3 * s + 1];
        float rz = pos[3 * t + 2] - pos[3 * s + 2];
        float best = 3.4e38f; int bk = 0;
        #pragma unroll
        for (int kp = 0; kp < PK; kp++) {
            float dx = rx - s_kpts[3 * kp + 0];
            float dy = ry - s_kpts[3 * kp + 1];
            float dz = rz - s_kpts[3 * kp + 2];
            float d2 = dx * dx + dy * dy + dz * dz;
            if (d2 < best) { best = d2; bk = kp; }
        }
        float w = fmaxf(1.0f - sqrtf(best) * 1.5f, 0.0f);   // 1/KP_EXTENT = 1.5
        atomicAdd(&s_coef[(el & ~(PK - 1)) + bk], w);
    }
    __syncthreads();

    // ---- GEMM: out[c,:] = sum_k coef[c,k] * x[srcs[c,k]] @ W[k] (bf16x3) ----
    const int wm = wid & 1;           // M warp tile (2 x 32 rows)
    const int wn = wid >> 1;          // N warp tile (4 x 32 cols)
    const uint32_t a_off[2] = {
        (uint32_t)(AH_OFF + (wm * 32 + 0  + (lane & 15)) * LDB + (lane >> 4) * 16),
        (uint32_t)(AH_OFF + (wm * 32 + 16 + (lane & 15)) * LDB + (lane >> 4) * 16)};
    const uint32_t b_off[2] = {
        (uint32_t)(BH_OFF + (wn * 32 + 0  + ((lane >> 4) << 3) + (lane & 7)) * LDB + ((lane >> 3) & 1) * 16),
        (uint32_t)(BH_OFF + (wn * 32 + 16 + ((lane >> 4) << 3) + (lane & 7)) * LDB + ((lane >> 3) & 1) * 16)};
    const uint32_t AL_DELTA = A_BYTES;   // AH -> AL
    const uint32_t BL_DELTA = B_BYTES;   // BH -> BL

    float acc[2][4][4];
    #pragma unroll
    for (int mt = 0; mt < 2; mt++)
        #pragma unroll
        for (int nt = 0; nt < 4; nt++)
            #pragma unroll
            for (int q = 0; q < 4; q++) acc[mt][nt][q] = 0.0f;

    // A staging: thread owns row tid>>2, 16-float quarter (tid&3)
    const int arow = tid >> 2;
    const int aq   = tid & 3;
    // B staging: thread owns 8 chunks of 16B (4 hi + 4 lo)
    float4 av[4];
    float  asc;
    uint4  bv[8];

    // prologue: load k=0 into registers
    {
        int src = s_srcs[arow * PK + 0];
        asc = s_coef[arow * PK + 0];
        const float4* xp = (const float4*)(x + (size_t)src * IN_F + aq * 16);
        #pragma unroll
        for (int j = 0; j < 4; j++) av[j] = xp[j];
        const char* wh = (const char*)g_wt_hi;
        const char* wl = (const char*)g_wt_lo;
        #pragma unroll
        for (int j = 0; j < 4; j++) {
            int g = tid + j * NTH;
            int row = g >> 3, cch = g & 7;
            bv[j]     = *(const uint4*)(wh + row * 128 + cch * 16);
            bv[j + 4] = *(const uint4*)(wl + row * 128 + cch * 16);
        }
    }

    #pragma unroll 1
    for (int k = 0; k < PK; k++) {
        // ---- store registers (data for step k) into smem ----
        {
            float fv[16];
            #pragma unroll
            for (int j = 0; j < 4; j++) {
                fv[j * 4 + 0] = av[j].x * asc; fv[j * 4 + 1] = av[j].y * asc;
                fv[j * 4 + 2] = av[j].z * asc; fv[j * 4 + 3] = av[j].w * asc;
            }
            #pragma unroll
            for (int g = 0; g < 2; g++) {
                uint32_t hi[4], lo[4];
                #pragma unroll
                for (int e2 = 0; e2 < 4; e2++) {
                    float f0 = fv[g * 8 + e2 * 2], f1 = fv[g * 8 + e2 * 2 + 1];
                    __nv_bfloat16 h0 = __float2bfloat16(f0);
                    __nv_bfloat16 h1 = __float2bfloat16(f1);
                    __nv_bfloat162 hp; hp.x = h0; hp.y = h1;
                    __nv_bfloat162 lp;
                    lp.x = __float2bfloat16(f0 - __bfloat162float(h0));
                    lp.y = __float2bfloat16(f1 - __bfloat162float(h1));
                    hi[e2] = *(uint32_t*)&hp;
                    lo[e2] = *(uint32_t*)&lp;
                }
                *(uint4*)(sm + AH_OFF + arow * LDB + aq * 32 + g * 16) =
                    make_uint4(hi[0], hi[1], hi[2], hi[3]);
                *(uint4*)(sm + AL_OFF + arow * LDB + aq * 32 + g * 16) =
                    make_uint4(lo[0], lo[1], lo[2], lo[3]);
            }
            #pragma unroll
            for (int j = 0; j < 4; j++) {
                int g = tid + j * NTH;
                int row = g >> 3, cch = g & 7;
                *(uint4*)(sm + BH_OFF + row * LDB + cch * 16) = bv[j];
                *(uint4*)(sm + BL_OFF + row * LDB + cch * 16) = bv[j + 4];
            }
        }
        __syncthreads();

        // ---- issue next step's global loads (outstanding across compute) ----
        if (k + 1 < PK) {
            int src = s_srcs[arow * PK + k + 1];
            asc = s_coef[arow * PK + k + 1];
            const float4* xp = (const float4*)(x + (size_t)src * IN_F + aq * 16);
            #pragma unroll
            for (int j = 0; j < 4; j++) av[j] = xp[j];
            const char* wh = (const char*)g_wt_hi + (size_t)(k + 1) * (OUT_F * IN_F * 2);
            const char* wl = (const char*)g_wt_lo + (size_t)(k + 1) * (OUT_F * IN_F * 2);
            #pragma unroll
            for (int j = 0; j < 4; j++) {
                int g = tid + j * NTH;
                int row = g >> 3, cch = g & 7;
                bv[j]     = *(const uint4*)(wh + row * 128 + cch * 16);
                bv[j + 4] = *(const uint4*)(wl + row * 128 + cch * 16);
            }
        }

        // ---- compute on smem tiles ----
        #pragma unroll
        for (int ks = 0; ks < 4; ks++) {
            const uint32_t i0 = ks * 32;   // 16 bf16 = 32 bytes
            uint32_t ah[2][4], al[2][4], bh[2][4], bl[2][4];
            #pragma unroll
            for (int mt = 0; mt < 2; mt++) {
                ldsm4(ah[mt], smb + a_off[mt] + i0);
                ldsm4(al[mt], smb + a_off[mt] + AL_DELTA + i0);
            }
            #pragma unroll
            for (int h = 0; h < 2; h++) {
                ldsm4(bh[h], smb + b_off[h] + i0);
                ldsm4(bl[h], smb + b_off[h] + BL_DELTA + i0);
            }
            #pragma unroll
            for (int mt = 0; mt < 2; mt++)
                #pragma unroll
                for (int nt = 0; nt < 4; nt++) {
                    const uint32_t* bhf = &bh[nt >> 1][(nt & 1) * 2];
                    const uint32_t* blf = &bl[nt >> 1][(nt & 1) * 2];
                    mma_bf16(acc[mt][nt], ah[mt], bhf);
                    mma_bf16(acc[mt][nt], ah[mt], blf);
                    mma_bf16(acc[mt][nt], al[mt], bhf);
                }
        }
        __syncthreads();
    }

    // ---- epilogue: direct f32 stores ----------------------------------------
    #pragma unroll
    for (int mt = 0; mt < 2; mt++) {
        int row = c0 + wm * 32 + mt * 16 + (lane >> 2);
        #pragma unroll
        for (int nt = 0; nt < 4; nt++) {
            int col = wn * 32 + nt * 8 + (lane & 3) * 2;
            float2 v0 = make_float2(acc[mt][nt][0], acc[mt][nt][1]);
            float2 v1 = make_float2(acc[mt][nt][2], acc[mt][nt][3]);
            *(float2*)(out + (size_t)row * OUT_F + col)       = v0;
            *(float2*)(out + (size_t)(row + 8) * OUT_F + col) = v1;
        }
    }
}

extern "C" void kernel_launch(void* const* d_in, const int* in_sizes, int n_in,
                              void* d_out, int out_size) {
    const float* x             = (const float*)d_in[0];
    const float* pos           = (const float*)d_in[1];
    const int*   edge_src      = (const int*)d_in[2];
    const int*   edge_tgt      = (const int*)d_in[3];
    const float* kernel_pts    = (const float*)d_in[4];
    const float* kernel_weight = (const float*)d_in[5];
    float* out = (float*)d_out;

    wsplit_kernel<<<(PK * OUT_F * IN_F + 255) / 256, 256>>>(kernel_weight);

    cudaFuncSetAttribute(kpconv_hmma_kernel,
                         cudaFuncAttributeMaxDynamicSharedMemorySize, SM_TOTAL);
    kpconv_hmma_kernel<<<NCENT / M_TILE, NTH, SM_TOTAL>>>(
        x, pos, edge_src, edge_tgt, kernel_pts, out);
}